// round 12
// baseline (speedup 1.0000x reference)
#include <cuda_runtime.h>
#include <cuda_fp16.h>
#include <mma.h>

using namespace nvcuda;

#define MAX_N 100000
#define PAD_N (MAX_N + 128)
#define MAX_E 1600000
#define IN_DIM 256
#define HID 128
#define OUTD 64

// Scratch in device globals. Atomics touch ONLY these.
__device__ __align__(16) int    g_deg[MAX_N];
__device__ __align__(16) int    g_rowstart[MAX_N];
__device__ __align__(16) int    g_cursor[MAX_N];
__device__ __align__(16) int2   g_csr[MAX_E];      // (src, __float_as_int(w))
__device__ __align__(16) float  g_dinv[MAX_N];
__device__ int g_total;
__device__ int g_is_i32;

// Activations fp16; rows padded (zero-init, never written past n) for unguarded tiles
__device__ __align__(16) __half g_h1[(size_t)PAD_N * HID];
__device__ __align__(16) __half g_agg1[(size_t)PAD_N * HID];
__device__ __align__(16) __half g_h2[(size_t)PAD_N * OUTD];
__device__ __align__(16) __half g_W2h[HID * OUTD];

// ---------------------------------------------------------------------------
// Fused init: zero degrees, detect edge dtype (block 0), convert W2 to fp16.
// ---------------------------------------------------------------------------
__global__ void init_kernel(const void* __restrict__ ei, const float* __restrict__ W2,
                            int E, int n) {
    int i = blockIdx.x * blockDim.x + threadIdx.x;
    if (i < n) g_deg[i] = 0;
    if (i < HID * OUTD) g_W2h[i] = __float2half(W2[i]);
    if (i == 0) g_total = 0;
    if (blockIdx.x == 0) {
        const unsigned long long* p = (const unsigned long long*)ei;
        __shared__ int found;
        if (threadIdx.x == 0) found = 0;
        __syncthreads();
        int lim = E < 4096 ? E : 4096;
        for (int j = threadIdx.x; j < lim; j += blockDim.x)
            if ((p[j] >> 32) != 0ULL) found = 1;
        __syncthreads();
        if (threadIdx.x == 0) g_is_i32 = found;
    }
}

__global__ void count_kernel(const void* __restrict__ ei, int E, int n) {
    int e = blockIdx.x * blockDim.x + threadIdx.x;
    if (e >= E) return;
    int d = g_is_i32 ? ((const int*)ei)[E + e] : (int)((const long long*)ei)[E + e];
    if ((unsigned)d < (unsigned)n) atomicAdd(&g_deg[d], 1);
}

__global__ void node_setup_kernel(int n) {
    int i = blockIdx.x * blockDim.x + threadIdx.x;
    if (i < n) {
        int d = g_deg[i];
        g_dinv[i] = rsqrtf((float)d + 1.0f);
        int base = atomicAdd(&g_total, d);
        g_rowstart[i] = base;
        g_cursor[i] = base;
    }
}

__global__ void fill_kernel(const void* __restrict__ ei, int E, int n) {
    int e = blockIdx.x * blockDim.x + threadIdx.x;
    if (e >= E) return;
    int s, d;
    if (g_is_i32) {
        const int* p = (const int*)ei;
        s = p[e]; d = p[E + e];
    } else {
        const long long* p = (const long long*)ei;
        s = (int)p[e]; d = (int)p[E + e];
    }
    if ((unsigned)s >= (unsigned)n || (unsigned)d >= (unsigned)n) return;
    float w = g_dinv[s] * g_dinv[d];
    int pos = atomicAdd(&g_cursor[d], 1);
    g_csr[pos] = make_int2(s, __float_as_int(w));
}

// ---------------------------------------------------------------------------
// Warp-per-node gathers, deep software pipeline (fp16 in, fp32 acc)
// ---------------------------------------------------------------------------
__global__ void gather1_kernel(const float* __restrict__ b1, int n) {
    int warp = (int)((blockIdx.x * blockDim.x + threadIdx.x) >> 5);
    int lane = threadIdx.x & 31;
    if (warp >= n) return;
    const __half2* __restrict__ hp = (const __half2*)g_h1;
    int start = g_rowstart[warp];
    int len = g_deg[warp];
    float di = g_dinv[warp];
    float s2 = di * di;
    long long self = (long long)warp * 64 + 2 * lane;
    float2 a0 = __half22float2(hp[self]);
    float2 a1 = __half22float2(hp[self + 1]);
    float4 acc = make_float4(a0.x * s2, a0.y * s2, a1.x * s2, a1.y * s2);
    const int2* __restrict__ csr = g_csr + start;

    int j = 0;
    for (; j + 4 <= len; j += 4) {
        int2 e0 = csr[j], e1 = csr[j + 1], e2 = csr[j + 2], e3 = csr[j + 3];
        long long r0 = (long long)e0.x * 64 + 2 * lane;
        long long r1 = (long long)e1.x * 64 + 2 * lane;
        long long r2 = (long long)e2.x * 64 + 2 * lane;
        long long r3 = (long long)e3.x * 64 + 2 * lane;
        __half2 p00 = hp[r0], p01 = hp[r0 + 1];
        __half2 p10 = hp[r1], p11 = hp[r1 + 1];
        __half2 p20 = hp[r2], p21 = hp[r2 + 1];
        __half2 p30 = hp[r3], p31 = hp[r3 + 1];
        float w0 = __int_as_float(e0.y), w1 = __int_as_float(e1.y);
        float w2 = __int_as_float(e2.y), w3 = __int_as_float(e3.y);
        float2 v;
        v = __half22float2(p00); acc.x = fmaf(v.x, w0, acc.x); acc.y = fmaf(v.y, w0, acc.y);
        v = __half22float2(p01); acc.z = fmaf(v.x, w0, acc.z); acc.w = fmaf(v.y, w0, acc.w);
        v = __half22float2(p10); acc.x = fmaf(v.x, w1, acc.x); acc.y = fmaf(v.y, w1, acc.y);
        v = __half22float2(p11); acc.z = fmaf(v.x, w1, acc.z); acc.w = fmaf(v.y, w1, acc.w);
        v = __half22float2(p20); acc.x = fmaf(v.x, w2, acc.x); acc.y = fmaf(v.y, w2, acc.y);
        v = __half22float2(p21); acc.z = fmaf(v.x, w2, acc.z); acc.w = fmaf(v.y, w2, acc.w);
        v = __half22float2(p30); acc.x = fmaf(v.x, w3, acc.x); acc.y = fmaf(v.y, w3, acc.y);
        v = __half22float2(p31); acc.z = fmaf(v.x, w3, acc.z); acc.w = fmaf(v.y, w3, acc.w);
    }
    for (; j < len; j++) {
        int2 e0 = csr[j];
        float w0 = __int_as_float(e0.y);
        long long r0 = (long long)e0.x * 64 + 2 * lane;
        float2 v0 = __half22float2(hp[r0]);
        float2 v1 = __half22float2(hp[r0 + 1]);
        acc.x = fmaf(v0.x, w0, acc.x);
        acc.y = fmaf(v0.y, w0, acc.y);
        acc.z = fmaf(v1.x, w0, acc.z);
        acc.w = fmaf(v1.y, w0, acc.w);
    }
    float4 bb = ((const float4*)b1)[lane];
    acc.x = fmaxf(acc.x + bb.x, 0.0f);
    acc.y = fmaxf(acc.y + bb.y, 0.0f);
    acc.z = fmaxf(acc.z + bb.z, 0.0f);
    acc.w = fmaxf(acc.w + bb.w, 0.0f);
    __half2* op = (__half2*)g_agg1;
    op[self] = __floats2half2_rn(acc.x, acc.y);
    op[self + 1] = __floats2half2_rn(acc.z, acc.w);
}

__global__ void gather2_kernel(const float* __restrict__ b2,
                               float* __restrict__ out, int n) {
    int warp = (int)((blockIdx.x * blockDim.x + threadIdx.x) >> 5);
    int lane = threadIdx.x & 31;
    if (warp >= n) return;
    const __half2* __restrict__ hp = (const __half2*)g_h2;
    int start = g_rowstart[warp];
    int len = g_deg[warp];
    float di = g_dinv[warp];
    float s2 = di * di;
    long long self = (long long)warp * 32 + lane;
    float2 acc = __half22float2(hp[self]);
    acc.x *= s2; acc.y *= s2;
    const int2* __restrict__ csr = g_csr + start;

    int j = 0;
    for (; j + 8 <= len; j += 8) {
        __half2 p[8];
        float w[8];
#pragma unroll
        for (int t = 0; t < 8; t++) {
            int2 ed = csr[j + t];
            w[t] = __int_as_float(ed.y);
            p[t] = hp[(long long)ed.x * 32 + lane];
        }
#pragma unroll
        for (int t = 0; t < 8; t++) {
            float2 v = __half22float2(p[t]);
            acc.x = fmaf(v.x, w[t], acc.x);
            acc.y = fmaf(v.y, w[t], acc.y);
        }
    }
    for (; j < len; j++) {
        int2 ed = csr[j];
        float w = __int_as_float(ed.y);
        float2 v = __half22float2(hp[(long long)ed.x * 32 + lane]);
        acc.x = fmaf(v.x, w, acc.x);
        acc.y = fmaf(v.y, w, acc.y);
    }
    float2 bb = ((const float2*)b2)[lane];
    acc.x += bb.x;
    acc.y += bb.y;
    ((float2*)out)[self] = acc;
}

// ---------------------------------------------------------------------------
// GEMM1: tf32 wmma, 128x64 tile, 8 warps (4x2), BK=32. fp32 in, fp16 out.
// Epilogue: per-warp 16x16 smem staging -> packed uint4 half stores.
// ---------------------------------------------------------------------------
__global__ __launch_bounds__(256) void tf32_gemm_h_kernel(
    int M, const float* __restrict__ A, const float* __restrict__ B,
    __half* __restrict__ C) {
    constexpr int K = IN_DIM, N = HID;
    constexpr int BM = 128, BN = 64, BK = 32;
    constexpr int LDA = BK + 4;   // 36 (mult of 4 for wmma ldm)
    constexpr int LDB = BN + 4;   // 68
    __shared__ float As[BM * LDA];            // 18.4KB
    __shared__ float Bs[BK * LDB];            // 8.7KB
    __shared__ float Stage[8][16 * 16];       // 8KB, per-warp epilogue staging

    const int tid = threadIdx.x;
    const int wid = tid >> 5;
    const int lane = tid & 31;
    const int wm = wid >> 1;       // 0..3 (32-row strip)
    const int wn = wid & 1;        // 0..1 (32-col strip)
    const int row0 = blockIdx.y * BM;
    const int col0 = blockIdx.x * BN;

    wmma::fragment<wmma::accumulator, 16, 16, 8, float> acc[2][2];
#pragma unroll
    for (int i = 0; i < 2; i++)
#pragma unroll
        for (int j = 0; j < 2; j++) wmma::fill_fragment(acc[i][j], 0.0f);

    for (int k0 = 0; k0 < K; k0 += BK) {
        // A tile 128x32 = 1024 float4, 4 per thread
#pragma unroll
        for (int i = 0; i < 4; i++) {
            int lin = tid + i * 256;
            int r = lin >> 3;              // 8 float4 per row
            int c4 = (lin & 7) << 2;
            float4 v = make_float4(0.f, 0.f, 0.f, 0.f);
            if (row0 + r < M)
                v = *reinterpret_cast<const float4*>(&A[(long long)(row0 + r) * K + k0 + c4]);
            As[r * LDA + c4 + 0] = v.x;
            As[r * LDA + c4 + 1] = v.y;
            As[r * LDA + c4 + 2] = v.z;
            As[r * LDA + c4 + 3] = v.w;
        }
        // B tile 32x64 = 512 float4, 2 per thread
#pragma unroll
        for (int i = 0; i < 2; i++) {
            int lin = tid + i * 256;
            int kk = lin >> 4;             // 16 float4 per row
            int c4 = (lin & 15) << 2;
            float4 v = *reinterpret_cast<const float4*>(&B[(long long)(k0 + kk) * N + col0 + c4]);
            Bs[kk * LDB + c4 + 0] = v.x;
            Bs[kk * LDB + c4 + 1] = v.y;
            Bs[kk * LDB + c4 + 2] = v.z;
            Bs[kk * LDB + c4 + 3] = v.w;
        }
        __syncthreads();

#pragma unroll
        for (int ks = 0; ks < BK; ks += 8) {
            wmma::fragment<wmma::matrix_a, 16, 16, 8, wmma::precision::tf32, wmma::row_major> af[2];
            wmma::fragment<wmma::matrix_b, 16, 16, 8, wmma::precision::tf32, wmma::row_major> bf[2];
#pragma unroll
            for (int i = 0; i < 2; i++) {
                wmma::load_matrix_sync(af[i], &As[(wm * 32 + i * 16) * LDA + ks], LDA);
#pragma unroll
                for (int t = 0; t < af[i].num_elements; t++)
                    af[i].x[t] = wmma::__float_to_tf32(af[i].x[t]);
            }
#pragma unroll
            for (int j = 0; j < 2; j++) {
                wmma::load_matrix_sync(bf[j], &Bs[ks * LDB + wn * 32 + j * 16], LDB);
#pragma unroll
                for (int t = 0; t < bf[j].num_elements; t++)
                    bf[j].x[t] = wmma::__float_to_tf32(bf[j].x[t]);
            }
#pragma unroll
            for (int i = 0; i < 2; i++)
#pragma unroll
                for (int j = 0; j < 2; j++)
                    wmma::mma_sync(acc[i][j], af[i], bf[j], acc[i][j]);
        }
        __syncthreads();
    }

    // Epilogue: fragment -> per-warp smem -> fp16 uint4 store.
    // Lane l covers linear elems [8l, 8l+8) of a 16x16 tile: r=l/2, c=(l&1)*8.
#pragma unroll
    for (int i = 0; i < 2; i++)
#pragma unroll
        for (int j = 0; j < 2; j++) {
            wmma::store_matrix_sync(Stage[wid], acc[i][j], 16, wmma::mem_row_major);
            __syncwarp();
            const float* s = &Stage[wid][lane * 8];
            __half2 hh[4];
            hh[0] = __floats2half2_rn(s[0], s[1]);
            hh[1] = __floats2half2_rn(s[2], s[3]);
            hh[2] = __floats2half2_rn(s[4], s[5]);
            hh[3] = __floats2half2_rn(s[6], s[7]);
            uint4 pk = *reinterpret_cast<const uint4*>(hh);
            int r = row0 + wm * 32 + i * 16 + (lane >> 1);
            int c = col0 + wn * 32 + j * 16 + (lane & 1) * 8;
            *reinterpret_cast<uint4*>(&C[(long long)r * N + c]) = pk;   // rows padded
            __syncwarp();
        }
}

// ---------------------------------------------------------------------------
// GEMM2: fp16 wmma m16n16k16, A=g_agg1, B=g_W2h, C=g_h2. 64x64 tile.
// ---------------------------------------------------------------------------
__global__ void h16_gemm_kernel(int M) {
    constexpr int K = HID, N = OUTD;
    constexpr int BM = 64, BN = 64, BK = 32;
    constexpr int LDA = BK + 8, LDB = BN + 8;
    __shared__ __half Ah[BM * LDA];
    __shared__ __half Bh[BK * LDB];
    __shared__ float Cs[BM * BN];

    const int tid = threadIdx.x;
    const int wid = tid >> 5;
    const int wm = wid >> 1, wn = wid & 1;
    const int row0 = blockIdx.x * BM;

    wmma::fragment<wmma::accumulator, 16, 16, 16, float> acc[2][2];
#pragma unroll
    for (int i = 0; i < 2; i++)
#pragma unroll
        for (int j = 0; j < 2; j++) wmma::fill_fragment(acc[i][j], 0.0f);

    const __half* A = g_agg1;
    for (int k0 = 0; k0 < K; k0 += BK) {
#pragma unroll
        for (int i = 0; i < 2; i++) {
            int lin = tid + i * 128;
            int r = lin >> 2;
            int c8 = (lin & 3) << 3;
            uint4 v = *reinterpret_cast<const uint4*>(&A[(long long)(row0 + r) * K + k0 + c8]);
            *reinterpret_cast<uint4*>(&Ah[r * LDA + c8]) = v;
        }
#pragma unroll
        for (int i = 0; i < 2; i++) {
            int lin = tid + i * 128;
            int kk = lin >> 3;
            int c8 = (lin & 7) << 3;
            uint4 v = *reinterpret_cast<const uint4*>(&g_W2h[(k0 + kk) * N + c8]);
            *reinterpret_cast<uint4*>(&Bh[kk * LDB + c8]) = v;
        }
        __syncthreads();

#pragma unroll
        for (int ks = 0; ks < BK; ks += 16) {
            wmma::fragment<wmma::matrix_a, 16, 16, 16, __half, wmma::row_major> af[2];
            wmma::fragment<wmma::matrix_b, 16, 16, 16, __half, wmma::row_major> bf[2];
#pragma unroll
            for (int i = 0; i < 2; i++)
                wmma::load_matrix_sync(af[i], &Ah[(wm * 32 + i * 16) * LDA + ks], LDA);
#pragma unroll
            for (int j = 0; j < 2; j++)
                wmma::load_matrix_sync(bf[j], &Bh[ks * LDB + wn * 32 + j * 16], LDB);
#pragma unroll
            for (int i = 0; i < 2; i++)
#pragma unroll
                for (int j = 0; j < 2; j++)
                    wmma::mma_sync(acc[i][j], af[i], bf[j], acc[i][j]);
        }
        __syncthreads();
    }

#pragma unroll
    for (int i = 0; i < 2; i++)
#pragma unroll
        for (int j = 0; j < 2; j++)
            wmma::store_matrix_sync(&Cs[(wm * 32 + i * 16) * BN + wn * 32 + j * 16],
                                    acc[i][j], BN, wmma::mem_row_major);
    __syncthreads();
    __half2* C2 = (__half2*)g_h2;
#pragma unroll
    for (int i = 0; i < 16; i++) {
        int lin = tid + i * 128;
        int r = lin >> 5;
        int c2 = lin & 31;
        float lo = Cs[r * BN + 2 * c2];
        float hi = Cs[r * BN + 2 * c2 + 1];
        C2[(long long)(row0 + r) * (N >> 1) + c2] = __floats2half2_rn(lo, hi);
    }
}

// ---------------------------------------------------------------------------
// Launch
// ---------------------------------------------------------------------------
extern "C" void kernel_launch(void* const* d_in, const int* in_sizes, int n_in,
                              void* d_out, int out_size) {
    const float* x = (const float*)d_in[0];
    const void* ei = d_in[1];
    const float* W1 = (const float*)d_in[2];
    const float* b1 = (const float*)d_in[3];
    const float* W2 = (const float*)d_in[4];
    const float* b2 = (const float*)d_in[5];
    float* out = (float*)d_out;

    const int Nn = in_sizes[0] / IN_DIM;   // 100000
    const int E = in_sizes[1] / 2;         // 1600000
    const int TB = 256;

    __half* h1_p;
    cudaGetSymbolAddress((void**)&h1_p, g_h1);

    // 1: fused init
    init_kernel<<<(Nn + TB - 1) / TB, TB>>>(ei, W2, E, Nn);
    // 2: GEMM1 (128x64 tiles, col tiles in x)
    {
        dim3 grid(HID / 64, (Nn + 127) / 128);
        tf32_gemm_h_kernel<<<grid, 256>>>(Nn, x, W1, h1_p);
    }
    // 3-5: CSR build
    count_kernel<<<(E + TB - 1) / TB, TB>>>(ei, E, Nn);
    node_setup_kernel<<<(Nn + TB - 1) / TB, TB>>>(Nn);
    fill_kernel<<<(E + TB - 1) / TB, TB>>>(ei, E, Nn);
    // 6: gather1
    {
        int blocks = (Nn + (TB / 32) - 1) / (TB / 32);
        gather1_kernel<<<blocks, TB>>>(b1, Nn);
    }
    // 7: GEMM2
    h16_gemm_kernel<<<(Nn + 63) / 64, 128>>>(Nn);
    // 8: gather2 -> d_out
    {
        int blocks = (Nn + (TB / 32) - 1) / (TB / 32);
        gather2_kernel<<<blocks, TB>>>(b2, out, Nn);
    }
}

// round 14
// speedup vs baseline: 1.0810x; 1.0810x over previous
#include <cuda_runtime.h>
#include <cuda_fp16.h>
#include <mma.h>

using namespace nvcuda;

#define MAX_N 100000
#define PAD_N (MAX_N + 128)
#define MAX_E 1600000
#define IN_DIM 256
#define HID 128
#define OUTD 64

// Scratch in device globals. Atomics touch ONLY these.
__device__ __align__(16) int    g_deg[MAX_N];
__device__ __align__(16) int    g_rowstart[MAX_N];
__device__ __align__(16) int    g_cursor[MAX_N];
__device__ __align__(16) int2   g_csr[MAX_E];      // (src, __float_as_int(w))
__device__ __align__(16) float  g_dinv[MAX_N];
__device__ int g_total;
__device__ int g_is_i32;

// Activations fp16; rows padded (zero-init, never written past n) for unguarded tiles
__device__ __align__(16) __half g_h1[(size_t)PAD_N * HID];
__device__ __align__(16) __half g_agg1[(size_t)PAD_N * HID];
__device__ __align__(16) __half g_h2[(size_t)PAD_N * OUTD];
__device__ __align__(16) __half g_W2h[HID * OUTD];

// ---------------------------------------------------------------------------
// Fused init: zero degrees, detect edge dtype (block 0), convert W2 to fp16.
// ---------------------------------------------------------------------------
__global__ void init_kernel(const void* __restrict__ ei, const float* __restrict__ W2,
                            int E, int n) {
    int i = blockIdx.x * blockDim.x + threadIdx.x;
    if (i < n) g_deg[i] = 0;
    if (i < HID * OUTD) g_W2h[i] = __float2half(W2[i]);
    if (i == 0) g_total = 0;
    if (blockIdx.x == 0) {
        const unsigned long long* p = (const unsigned long long*)ei;
        __shared__ int found;
        if (threadIdx.x == 0) found = 0;
        __syncthreads();
        int lim = E < 4096 ? E : 4096;
        for (int j = threadIdx.x; j < lim; j += blockDim.x)
            if ((p[j] >> 32) != 0ULL) found = 1;
        __syncthreads();
        if (threadIdx.x == 0) g_is_i32 = found;
    }
}

__global__ void count_kernel(const void* __restrict__ ei, int E, int n) {
    int e = blockIdx.x * blockDim.x + threadIdx.x;
    if (e >= E) return;
    int d = g_is_i32 ? ((const int*)ei)[E + e] : (int)((const long long*)ei)[E + e];
    if ((unsigned)d < (unsigned)n) atomicAdd(&g_deg[d], 1);
}

__global__ void node_setup_kernel(int n) {
    int i = blockIdx.x * blockDim.x + threadIdx.x;
    if (i < n) {
        int d = g_deg[i];
        g_dinv[i] = rsqrtf((float)d + 1.0f);
        int base = atomicAdd(&g_total, d);
        g_rowstart[i] = base;
        g_cursor[i] = base;
    }
}

__global__ void fill_kernel(const void* __restrict__ ei, int E, int n) {
    int e = blockIdx.x * blockDim.x + threadIdx.x;
    if (e >= E) return;
    int s, d;
    if (g_is_i32) {
        const int* p = (const int*)ei;
        s = p[e]; d = p[E + e];
    } else {
        const long long* p = (const long long*)ei;
        s = (int)p[e]; d = (int)p[E + e];
    }
    if ((unsigned)s >= (unsigned)n || (unsigned)d >= (unsigned)n) return;
    float w = g_dinv[s] * g_dinv[d];
    int pos = atomicAdd(&g_cursor[d], 1);
    g_csr[pos] = make_int2(s, __float_as_int(w));
}

// ---------------------------------------------------------------------------
// Warp-per-node gathers (R10-winning versions: depth-2 / depth-4 pipelines)
// ---------------------------------------------------------------------------
__global__ void gather1_kernel(const float* __restrict__ b1, int n) {
    int warp = (int)((blockIdx.x * blockDim.x + threadIdx.x) >> 5);
    int lane = threadIdx.x & 31;
    if (warp >= n) return;
    const __half2* __restrict__ hp = (const __half2*)g_h1;
    int start = g_rowstart[warp];
    int len = g_deg[warp];
    float di = g_dinv[warp];
    float s2 = di * di;
    long long self = (long long)warp * 64 + 2 * lane;
    float2 a0 = __half22float2(hp[self]);
    float2 a1 = __half22float2(hp[self + 1]);
    float4 acc = make_float4(a0.x * s2, a0.y * s2, a1.x * s2, a1.y * s2);
    const int2* __restrict__ csr = g_csr + start;

    int j = 0;
    for (; j + 2 <= len; j += 2) {
        int2 e0 = csr[j];
        int2 e1 = csr[j + 1];
        long long b0 = (long long)e0.x * 64 + 2 * lane;
        long long b1o = (long long)e1.x * 64 + 2 * lane;
        __half2 p00 = hp[b0], p01 = hp[b0 + 1];
        __half2 p10 = hp[b1o], p11 = hp[b1o + 1];
        float w0 = __int_as_float(e0.y);
        float w1 = __int_as_float(e1.y);
        float2 v;
        v = __half22float2(p00); acc.x = fmaf(v.x, w0, acc.x); acc.y = fmaf(v.y, w0, acc.y);
        v = __half22float2(p01); acc.z = fmaf(v.x, w0, acc.z); acc.w = fmaf(v.y, w0, acc.w);
        v = __half22float2(p10); acc.x = fmaf(v.x, w1, acc.x); acc.y = fmaf(v.y, w1, acc.y);
        v = __half22float2(p11); acc.z = fmaf(v.x, w1, acc.z); acc.w = fmaf(v.y, w1, acc.w);
    }
    if (j < len) {
        int2 e0 = csr[j];
        float w0 = __int_as_float(e0.y);
        long long b0 = (long long)e0.x * 64 + 2 * lane;
        float2 v0 = __half22float2(hp[b0]);
        float2 v1 = __half22float2(hp[b0 + 1]);
        acc.x = fmaf(v0.x, w0, acc.x);
        acc.y = fmaf(v0.y, w0, acc.y);
        acc.z = fmaf(v1.x, w0, acc.z);
        acc.w = fmaf(v1.y, w0, acc.w);
    }
    float4 bb = ((const float4*)b1)[lane];
    acc.x = fmaxf(acc.x + bb.x, 0.0f);
    acc.y = fmaxf(acc.y + bb.y, 0.0f);
    acc.z = fmaxf(acc.z + bb.z, 0.0f);
    acc.w = fmaxf(acc.w + bb.w, 0.0f);
    __half2* op = (__half2*)g_agg1;
    op[self] = __floats2half2_rn(acc.x, acc.y);
    op[self + 1] = __floats2half2_rn(acc.z, acc.w);
}

__global__ void gather2_kernel(const float* __restrict__ b2,
                               float* __restrict__ out, int n) {
    int warp = (int)((blockIdx.x * blockDim.x + threadIdx.x) >> 5);
    int lane = threadIdx.x & 31;
    if (warp >= n) return;
    const __half2* __restrict__ hp = (const __half2*)g_h2;
    int start = g_rowstart[warp];
    int len = g_deg[warp];
    float di = g_dinv[warp];
    float s2 = di * di;
    long long self = (long long)warp * 32 + lane;
    float2 acc = __half22float2(hp[self]);
    acc.x *= s2; acc.y *= s2;
    const int2* __restrict__ csr = g_csr + start;

    int j = 0;
    for (; j + 4 <= len; j += 4) {
        int2 e0 = csr[j], e1 = csr[j + 1], e2 = csr[j + 2], e3 = csr[j + 3];
        __half2 p0 = hp[(long long)e0.x * 32 + lane];
        __half2 p1 = hp[(long long)e1.x * 32 + lane];
        __half2 p2 = hp[(long long)e2.x * 32 + lane];
        __half2 p3 = hp[(long long)e3.x * 32 + lane];
        float2 v;
        v = __half22float2(p0); acc.x = fmaf(v.x, __int_as_float(e0.y), acc.x); acc.y = fmaf(v.y, __int_as_float(e0.y), acc.y);
        v = __half22float2(p1); acc.x = fmaf(v.x, __int_as_float(e1.y), acc.x); acc.y = fmaf(v.y, __int_as_float(e1.y), acc.y);
        v = __half22float2(p2); acc.x = fmaf(v.x, __int_as_float(e2.y), acc.x); acc.y = fmaf(v.y, __int_as_float(e2.y), acc.y);
        v = __half22float2(p3); acc.x = fmaf(v.x, __int_as_float(e3.y), acc.x); acc.y = fmaf(v.y, __int_as_float(e3.y), acc.y);
    }
    for (; j < len; j++) {
        int2 ed = csr[j];
        float w = __int_as_float(ed.y);
        float2 v = __half22float2(hp[(long long)ed.x * 32 + lane]);
        acc.x = fmaf(v.x, w, acc.x);
        acc.y = fmaf(v.y, w, acc.y);
    }
    float2 bb = ((const float2*)b2)[lane];
    acc.x += bb.x;
    acc.y += bb.y;
    ((float2*)out)[self] = acc;
}

// ---------------------------------------------------------------------------
// GEMM1: tf32 wmma, 64x64 tile, 4 warps, BK=32. Register double-buffered:
// next tile's global loads are issued before the MMA section each iteration.
// fp32 in, fp16 out via smem-staged epilogue (R10-winning epilogue).
// ---------------------------------------------------------------------------
__global__ void tf32_gemm_h_kernel(int M, int N, int K,
                                   const float* __restrict__ A,
                                   const float* __restrict__ B,
                                   __half* __restrict__ C) {
    constexpr int BM = 64, BN = 64, BK = 32;
    constexpr int LDA = BK + 8, LDB = BN + 8;
    __shared__ float As[BM * LDA];
    __shared__ float Bs[BK * LDB];
    __shared__ float Cs[BM * BN];

    const int tid = threadIdx.x;
    const int wid = tid >> 5;
    const int wm = wid >> 1, wn = wid & 1;
    const int row0 = blockIdx.y * BM;
    const int col0 = blockIdx.x * BN;

    wmma::fragment<wmma::accumulator, 16, 16, 8, float> acc[2][2];
#pragma unroll
    for (int i = 0; i < 2; i++)
#pragma unroll
        for (int j = 0; j < 2; j++) wmma::fill_fragment(acc[i][j], 0.0f);

    float4 ra[4], rb[4];
    // prologue: load k0 = 0 tile into registers
#pragma unroll
    for (int i = 0; i < 4; i++) {
        int lin = tid + i * 128;
        int r = lin >> 3;
        int c4 = (lin & 7) << 2;
        ra[i] = make_float4(0.f, 0.f, 0.f, 0.f);
        if (row0 + r < M)
            ra[i] = *reinterpret_cast<const float4*>(&A[(long long)(row0 + r) * K + c4]);
    }
#pragma unroll
    for (int i = 0; i < 4; i++) {
        int lin = tid + i * 128;
        int kk = lin >> 4;
        int c4 = (lin & 15) << 2;
        rb[i] = *reinterpret_cast<const float4*>(&B[(long long)kk * N + col0 + c4]);
    }

    for (int k0 = 0; k0 < K; k0 += BK) {
        // store current regs -> smem
#pragma unroll
        for (int i = 0; i < 4; i++) {
            int lin = tid + i * 128;
            int r = lin >> 3;
            int c4 = (lin & 7) << 2;
            As[r * LDA + c4 + 0] = ra[i].x;
            As[r * LDA + c4 + 1] = ra[i].y;
            As[r * LDA + c4 + 2] = ra[i].z;
            As[r * LDA + c4 + 3] = ra[i].w;
        }
#pragma unroll
        for (int i = 0; i < 4; i++) {
            int lin = tid + i * 128;
            int kk = lin >> 4;
            int c4 = (lin & 15) << 2;
            Bs[kk * LDB + c4 + 0] = rb[i].x;
            Bs[kk * LDB + c4 + 1] = rb[i].y;
            Bs[kk * LDB + c4 + 2] = rb[i].z;
            Bs[kk * LDB + c4 + 3] = rb[i].w;
        }
        __syncthreads();

        // issue NEXT tile's global loads (in flight during MMA below)
        int kn = k0 + BK;
        if (kn < K) {
#pragma unroll
            for (int i = 0; i < 4; i++) {
                int lin = tid + i * 128;
                int r = lin >> 3;
                int c4 = (lin & 7) << 2;
                ra[i] = make_float4(0.f, 0.f, 0.f, 0.f);
                if (row0 + r < M)
                    ra[i] = *reinterpret_cast<const float4*>(&A[(long long)(row0 + r) * K + kn + c4]);
            }
#pragma unroll
            for (int i = 0; i < 4; i++) {
                int lin = tid + i * 128;
                int kk = lin >> 4;
                int c4 = (lin & 15) << 2;
                rb[i] = *reinterpret_cast<const float4*>(&B[(long long)(kn + kk) * N + col0 + c4]);
            }
        }

#pragma unroll
        for (int ks = 0; ks < BK; ks += 8) {
            wmma::fragment<wmma::matrix_a, 16, 16, 8, wmma::precision::tf32, wmma::row_major> af[2];
            wmma::fragment<wmma::matrix_b, 16, 16, 8, wmma::precision::tf32, wmma::row_major> bf[2];
#pragma unroll
            for (int i = 0; i < 2; i++) {
                wmma::load_matrix_sync(af[i], &As[(wm * 32 + i * 16) * LDA + ks], LDA);
#pragma unroll
                for (int t = 0; t < af[i].num_elements; t++)
                    af[i].x[t] = wmma::__float_to_tf32(af[i].x[t]);
            }
#pragma unroll
            for (int j = 0; j < 2; j++) {
                wmma::load_matrix_sync(bf[j], &Bs[ks * LDB + wn * 32 + j * 16], LDB);
#pragma unroll
                for (int t = 0; t < bf[j].num_elements; t++)
                    bf[j].x[t] = wmma::__float_to_tf32(bf[j].x[t]);
            }
#pragma unroll
            for (int i = 0; i < 2; i++)
#pragma unroll
                for (int j = 0; j < 2; j++)
                    wmma::mma_sync(acc[i][j], af[i], bf[j], acc[i][j]);
        }
        __syncthreads();
    }

#pragma unroll
    for (int i = 0; i < 2; i++)
#pragma unroll
        for (int j = 0; j < 2; j++)
            wmma::store_matrix_sync(&Cs[(wm * 32 + i * 16) * BN + wn * 32 + j * 16],
                                    acc[i][j], BN, wmma::mem_row_major);
    __syncthreads();
    __half2* C2 = (__half2*)C;
    int ldc2 = N >> 1;
#pragma unroll
    for (int i = 0; i < 16; i++) {
        int lin = tid + i * 128;
        int r = lin >> 5;
        int c2 = lin & 31;
        float lo = Cs[r * BN + 2 * c2];
        float hi = Cs[r * BN + 2 * c2 + 1];
        C2[(long long)(row0 + r) * ldc2 + (col0 >> 1) + c2] = __floats2half2_rn(lo, hi);
    }
}

// ---------------------------------------------------------------------------
// GEMM2: fp16 wmma m16n16k16, A=g_agg1, B=g_W2h, C=g_h2. 64x64 tile.
// ---------------------------------------------------------------------------
__global__ void h16_gemm_kernel(int M) {
    constexpr int K = HID, N = OUTD;
    constexpr int BM = 64, BN = 64, BK = 32;
    constexpr int LDA = BK + 8, LDB = BN + 8;
    __shared__ __half Ah[BM * LDA];
    __shared__ __half Bh[BK * LDB];
    __shared__ float Cs[BM * BN];

    const int tid = threadIdx.x;
    const int wid = tid >> 5;
    const int wm = wid >> 1, wn = wid & 1;
    const int row0 = blockIdx.x * BM;

    wmma::fragment<wmma::accumulator, 16, 16, 16, float> acc[2][2];
#pragma unroll
    for (int i = 0; i < 2; i++)
#pragma unroll
        for (int j = 0; j < 2; j++) wmma::fill_fragment(acc[i][j], 0.0f);

    const __half* A = g_agg1;
    for (int k0 = 0; k0 < K; k0 += BK) {
#pragma unroll
        for (int i = 0; i < 2; i++) {
            int lin = tid + i * 128;
            int r = lin >> 2;
            int c8 = (lin & 3) << 3;
            uint4 v = *reinterpret_cast<const uint4*>(&A[(long long)(row0 + r) * K + k0 + c8]);
            *reinterpret_cast<uint4*>(&Ah[r * LDA + c8]) = v;
        }
#pragma unroll
        for (int i = 0; i < 2; i++) {
            int lin = tid + i * 128;
            int kk = lin >> 3;
            int c8 = (lin & 7) << 3;
            uint4 v = *reinterpret_cast<const uint4*>(&g_W2h[(k0 + kk) * N + c8]);
            *reinterpret_cast<uint4*>(&Bh[kk * LDB + c8]) = v;
        }
        __syncthreads();

#pragma unroll
        for (int ks = 0; ks < BK; ks += 16) {
            wmma::fragment<wmma::matrix_a, 16, 16, 16, __half, wmma::row_major> af[2];
            wmma::fragment<wmma::matrix_b, 16, 16, 16, __half, wmma::row_major> bf[2];
#pragma unroll
            for (int i = 0; i < 2; i++)
                wmma::load_matrix_sync(af[i], &Ah[(wm * 32 + i * 16) * LDA + ks], LDA);
#pragma unroll
            for (int j = 0; j < 2; j++)
                wmma::load_matrix_sync(bf[j], &Bh[ks * LDB + wn * 32 + j * 16], LDB);
#pragma unroll
            for (int i = 0; i < 2; i++)
#pragma unroll
                for (int j = 0; j < 2; j++)
                    wmma::mma_sync(acc[i][j], af[i], bf[j], acc[i][j]);
        }
        __syncthreads();
    }

#pragma unroll
    for (int i = 0; i < 2; i++)
#pragma unroll
        for (int j = 0; j < 2; j++)
            wmma::store_matrix_sync(&Cs[(wm * 32 + i * 16) * BN + wn * 32 + j * 16],
                                    acc[i][j], BN, wmma::mem_row_major);
    __syncthreads();
    __half2* C2 = (__half2*)g_h2;
#pragma unroll
    for (int i = 0; i < 16; i++) {
        int lin = tid + i * 128;
        int r = lin >> 5;
        int c2 = lin & 31;
        float lo = Cs[r * BN + 2 * c2];
        float hi = Cs[r * BN + 2 * c2 + 1];
        C2[(long long)(row0 + r) * (N >> 1) + c2] = __floats2half2_rn(lo, hi);
    }
}

// ---------------------------------------------------------------------------
// Launch
// ---------------------------------------------------------------------------
extern "C" void kernel_launch(void* const* d_in, const int* in_sizes, int n_in,
                              void* d_out, int out_size) {
    const float* x = (const float*)d_in[0];
    const void* ei = d_in[1];
    const float* W1 = (const float*)d_in[2];
    const float* b1 = (const float*)d_in[3];
    const float* W2 = (const float*)d_in[4];
    const float* b2 = (const float*)d_in[5];
    float* out = (float*)d_out;

    const int Nn = in_sizes[0] / IN_DIM;   // 100000
    const int E = in_sizes[1] / 2;         // 1600000
    const int TB = 256;

    __half* h1_p;
    cudaGetSymbolAddress((void**)&h1_p, g_h1);

    // 1: fused init
    init_kernel<<<(Nn + TB - 1) / TB, TB>>>(ei, W2, E, Nn);
    // 2: GEMM1 (64x64 tiles, register double-buffered)
    {
        dim3 grid(HID / 64, (Nn + 63) / 64);
        tf32_gemm_h_kernel<<<grid, 128>>>(Nn, HID, IN_DIM, x, W1, h1_p);
    }
    // 3-5: CSR build
    count_kernel<<<(E + TB - 1) / TB, TB>>>(ei, E, Nn);
    node_setup_kernel<<<(Nn + TB - 1) / TB, TB>>>(Nn);
    fill_kernel<<<(E + TB - 1) / TB, TB>>>(ei, E, Nn);
    // 6: gather1
    {
        int blocks = (Nn + (TB / 32) - 1) / (TB / 32);
        gather1_kernel<<<blocks, TB>>>(b1, Nn);
    }
    // 7: GEMM2
    h16_gemm_kernel<<<(Nn + 63) / 64, 128>>>(Nn);
    // 8: gather2 -> d_out
    {
        int blocks = (Nn + (TB / 32) - 1) / (TB / 32);
        gather2_kernel<<<blocks, TB>>>(b2, out, Nn);
    }
}

// round 16
// speedup vs baseline: 1.1367x; 1.0515x over previous
#include <cuda_runtime.h>
#include <cuda_fp16.h>
#include <mma.h>

using namespace nvcuda;

#define MAX_N 100000
#define PAD_N (MAX_N + 128)
#define MAX_E 1600000
#define IN_DIM 256
#define HID 128
#define OUTD 64

// Scratch in device globals. Atomics touch ONLY these.
__device__ __align__(16) int    g_deg[MAX_N];
__device__ __align__(16) int    g_rowstart[MAX_N];
__device__ __align__(16) int    g_cursor[MAX_N];
__device__ __align__(16) int2   g_csr[MAX_E];      // (src, __float_as_int(w))
__device__ __align__(16) float  g_dinv[MAX_N];
__device__ int g_total;
__device__ int g_is_i32;

// Activations fp16; rows padded (zero-init, never written past n) for unguarded tiles
__device__ __align__(16) __half g_h1[(size_t)PAD_N * HID];
__device__ __align__(16) __half g_agg1[(size_t)PAD_N * HID];
__device__ __align__(16) __half g_h2[(size_t)PAD_N * OUTD];
__device__ __align__(16) __half g_W2h[HID * OUTD];

// ---------------------------------------------------------------------------
// Fused init: zero degrees, detect edge dtype (block 0), convert W2 to fp16.
// ---------------------------------------------------------------------------
__global__ void init_kernel(const void* __restrict__ ei, const float* __restrict__ W2,
                            int E, int n) {
    int i = blockIdx.x * blockDim.x + threadIdx.x;
    if (i < n) g_deg[i] = 0;
    if (i < HID * OUTD) g_W2h[i] = __float2half(W2[i]);
    if (i == 0) g_total = 0;
    if (blockIdx.x == 0) {
        const unsigned long long* p = (const unsigned long long*)ei;
        __shared__ int found;
        if (threadIdx.x == 0) found = 0;
        __syncthreads();
        int lim = E < 4096 ? E : 4096;
        for (int j = threadIdx.x; j < lim; j += blockDim.x)
            if ((p[j] >> 32) != 0ULL) found = 1;
        __syncthreads();
        if (threadIdx.x == 0) g_is_i32 = found;
    }
}

__global__ void count_kernel(const void* __restrict__ ei, int E, int n) {
    int e = blockIdx.x * blockDim.x + threadIdx.x;
    if (e >= E) return;
    int d = g_is_i32 ? ((const int*)ei)[E + e] : (int)((const long long*)ei)[E + e];
    if ((unsigned)d < (unsigned)n) atomicAdd(&g_deg[d], 1);
}

__global__ void node_setup_kernel(int n) {
    int i = blockIdx.x * blockDim.x + threadIdx.x;
    if (i < n) {
        int d = g_deg[i];
        g_dinv[i] = rsqrtf((float)d + 1.0f);
        int base = atomicAdd(&g_total, d);
        g_rowstart[i] = base;
        g_cursor[i] = base;
    }
}

__global__ void fill_kernel(const void* __restrict__ ei, int E, int n) {
    int e = blockIdx.x * blockDim.x + threadIdx.x;
    if (e >= E) return;
    int s, d;
    if (g_is_i32) {
        const int* p = (const int*)ei;
        s = p[e]; d = p[E + e];
    } else {
        const long long* p = (const long long*)ei;
        s = (int)p[e]; d = (int)p[E + e];
    }
    if ((unsigned)s >= (unsigned)n || (unsigned)d >= (unsigned)n) return;
    float w = g_dinv[s] * g_dinv[d];
    int pos = atomicAdd(&g_cursor[d], 1);
    g_csr[pos] = make_int2(s, __float_as_int(w));
}

// ---------------------------------------------------------------------------
// Warp-per-node gathers (R10-winning versions: depth-2 / depth-4 pipelines)
// ---------------------------------------------------------------------------
__global__ void gather1_kernel(const float* __restrict__ b1, int n) {
    int warp = (int)((blockIdx.x * blockDim.x + threadIdx.x) >> 5);
    int lane = threadIdx.x & 31;
    if (warp >= n) return;
    const __half2* __restrict__ hp = (const __half2*)g_h1;
    int start = g_rowstart[warp];
    int len = g_deg[warp];
    float di = g_dinv[warp];
    float s2 = di * di;
    long long self = (long long)warp * 64 + 2 * lane;
    float2 a0 = __half22float2(hp[self]);
    float2 a1 = __half22float2(hp[self + 1]);
    float4 acc = make_float4(a0.x * s2, a0.y * s2, a1.x * s2, a1.y * s2);
    const int2* __restrict__ csr = g_csr + start;

    int j = 0;
    for (; j + 2 <= len; j += 2) {
        int2 e0 = csr[j];
        int2 e1 = csr[j + 1];
        long long b0 = (long long)e0.x * 64 + 2 * lane;
        long long b1o = (long long)e1.x * 64 + 2 * lane;
        __half2 p00 = hp[b0], p01 = hp[b0 + 1];
        __half2 p10 = hp[b1o], p11 = hp[b1o + 1];
        float w0 = __int_as_float(e0.y);
        float w1 = __int_as_float(e1.y);
        float2 v;
        v = __half22float2(p00); acc.x = fmaf(v.x, w0, acc.x); acc.y = fmaf(v.y, w0, acc.y);
        v = __half22float2(p01); acc.z = fmaf(v.x, w0, acc.z); acc.w = fmaf(v.y, w0, acc.w);
        v = __half22float2(p10); acc.x = fmaf(v.x, w1, acc.x); acc.y = fmaf(v.y, w1, acc.y);
        v = __half22float2(p11); acc.z = fmaf(v.x, w1, acc.z); acc.w = fmaf(v.y, w1, acc.w);
    }
    if (j < len) {
        int2 e0 = csr[j];
        float w0 = __int_as_float(e0.y);
        long long b0 = (long long)e0.x * 64 + 2 * lane;
        float2 v0 = __half22float2(hp[b0]);
        float2 v1 = __half22float2(hp[b0 + 1]);
        acc.x = fmaf(v0.x, w0, acc.x);
        acc.y = fmaf(v0.y, w0, acc.y);
        acc.z = fmaf(v1.x, w0, acc.z);
        acc.w = fmaf(v1.y, w0, acc.w);
    }
    float4 bb = ((const float4*)b1)[lane];
    acc.x = fmaxf(acc.x + bb.x, 0.0f);
    acc.y = fmaxf(acc.y + bb.y, 0.0f);
    acc.z = fmaxf(acc.z + bb.z, 0.0f);
    acc.w = fmaxf(acc.w + bb.w, 0.0f);
    __half2* op = (__half2*)g_agg1;
    op[self] = __floats2half2_rn(acc.x, acc.y);
    op[self + 1] = __floats2half2_rn(acc.z, acc.w);
}

__global__ void gather2_kernel(const float* __restrict__ b2,
                               float* __restrict__ out, int n) {
    int warp = (int)((blockIdx.x * blockDim.x + threadIdx.x) >> 5);
    int lane = threadIdx.x & 31;
    if (warp >= n) return;
    const __half2* __restrict__ hp = (const __half2*)g_h2;
    int start = g_rowstart[warp];
    int len = g_deg[warp];
    float di = g_dinv[warp];
    float s2 = di * di;
    long long self = (long long)warp * 32 + lane;
    float2 acc = __half22float2(hp[self]);
    acc.x *= s2; acc.y *= s2;
    const int2* __restrict__ csr = g_csr + start;

    int j = 0;
    for (; j + 4 <= len; j += 4) {
        int2 e0 = csr[j], e1 = csr[j + 1], e2 = csr[j + 2], e3 = csr[j + 3];
        __half2 p0 = hp[(long long)e0.x * 32 + lane];
        __half2 p1 = hp[(long long)e1.x * 32 + lane];
        __half2 p2 = hp[(long long)e2.x * 32 + lane];
        __half2 p3 = hp[(long long)e3.x * 32 + lane];
        float2 v;
        v = __half22float2(p0); acc.x = fmaf(v.x, __int_as_float(e0.y), acc.x); acc.y = fmaf(v.y, __int_as_float(e0.y), acc.y);
        v = __half22float2(p1); acc.x = fmaf(v.x, __int_as_float(e1.y), acc.x); acc.y = fmaf(v.y, __int_as_float(e1.y), acc.y);
        v = __half22float2(p2); acc.x = fmaf(v.x, __int_as_float(e2.y), acc.x); acc.y = fmaf(v.y, __int_as_float(e2.y), acc.y);
        v = __half22float2(p3); acc.x = fmaf(v.x, __int_as_float(e3.y), acc.x); acc.y = fmaf(v.y, __int_as_float(e3.y), acc.y);
    }
    for (; j < len; j++) {
        int2 ed = csr[j];
        float w = __int_as_float(ed.y);
        float2 v = __half22float2(hp[(long long)ed.x * 32 + lane]);
        acc.x = fmaf(v.x, w, acc.x);
        acc.y = fmaf(v.y, w, acc.y);
    }
    float2 bb = ((const float2*)b2)[lane];
    acc.x += bb.x;
    acc.y += bb.y;
    ((float2*)out)[self] = acc;
}

// ---------------------------------------------------------------------------
// GEMM1: tf32 wmma, 64x64 tile, 4 warps, BK=32, register double-buffered.
// fp32 in, fp16 out via smem-staged epilogue.
// ---------------------------------------------------------------------------
__global__ void tf32_gemm_h_kernel(int M, int N, int K,
                                   const float* __restrict__ A,
                                   const float* __restrict__ B,
                                   __half* __restrict__ C) {
    constexpr int BM = 64, BN = 64, BK = 32;
    constexpr int LDA = BK + 8, LDB = BN + 8;
    __shared__ float As[BM * LDA];
    __shared__ float Bs[BK * LDB];
    __shared__ float Cs[BM * BN];

    const int tid = threadIdx.x;
    const int wid = tid >> 5;
    const int wm = wid >> 1, wn = wid & 1;
    const int row0 = blockIdx.y * BM;
    const int col0 = blockIdx.x * BN;

    wmma::fragment<wmma::accumulator, 16, 16, 8, float> acc[2][2];
#pragma unroll
    for (int i = 0; i < 2; i++)
#pragma unroll
        for (int j = 0; j < 2; j++) wmma::fill_fragment(acc[i][j], 0.0f);

    float4 ra[4], rb[4];
#pragma unroll
    for (int i = 0; i < 4; i++) {
        int lin = tid + i * 128;
        int r = lin >> 3;
        int c4 = (lin & 7) << 2;
        ra[i] = make_float4(0.f, 0.f, 0.f, 0.f);
        if (row0 + r < M)
            ra[i] = *reinterpret_cast<const float4*>(&A[(long long)(row0 + r) * K + c4]);
    }
#pragma unroll
    for (int i = 0; i < 4; i++) {
        int lin = tid + i * 128;
        int kk = lin >> 4;
        int c4 = (lin & 15) << 2;
        rb[i] = *reinterpret_cast<const float4*>(&B[(long long)kk * N + col0 + c4]);
    }

    for (int k0 = 0; k0 < K; k0 += BK) {
#pragma unroll
        for (int i = 0; i < 4; i++) {
            int lin = tid + i * 128;
            int r = lin >> 3;
            int c4 = (lin & 7) << 2;
            As[r * LDA + c4 + 0] = ra[i].x;
            As[r * LDA + c4 + 1] = ra[i].y;
            As[r * LDA + c4 + 2] = ra[i].z;
            As[r * LDA + c4 + 3] = ra[i].w;
        }
#pragma unroll
        for (int i = 0; i < 4; i++) {
            int lin = tid + i * 128;
            int kk = lin >> 4;
            int c4 = (lin & 15) << 2;
            Bs[kk * LDB + c4 + 0] = rb[i].x;
            Bs[kk * LDB + c4 + 1] = rb[i].y;
            Bs[kk * LDB + c4 + 2] = rb[i].z;
            Bs[kk * LDB + c4 + 3] = rb[i].w;
        }
        __syncthreads();

        int kn = k0 + BK;
        if (kn < K) {
#pragma unroll
            for (int i = 0; i < 4; i++) {
                int lin = tid + i * 128;
                int r = lin >> 3;
                int c4 = (lin & 7) << 2;
                ra[i] = make_float4(0.f, 0.f, 0.f, 0.f);
                if (row0 + r < M)
                    ra[i] = *reinterpret_cast<const float4*>(&A[(long long)(row0 + r) * K + kn + c4]);
            }
#pragma unroll
            for (int i = 0; i < 4; i++) {
                int lin = tid + i * 128;
                int kk = lin >> 4;
                int c4 = (lin & 15) << 2;
                rb[i] = *reinterpret_cast<const float4*>(&B[(long long)(kn + kk) * N + col0 + c4]);
            }
        }

#pragma unroll
        for (int ks = 0; ks < BK; ks += 8) {
            wmma::fragment<wmma::matrix_a, 16, 16, 8, wmma::precision::tf32, wmma::row_major> af[2];
            wmma::fragment<wmma::matrix_b, 16, 16, 8, wmma::precision::tf32, wmma::row_major> bf[2];
#pragma unroll
            for (int i = 0; i < 2; i++) {
                wmma::load_matrix_sync(af[i], &As[(wm * 32 + i * 16) * LDA + ks], LDA);
#pragma unroll
                for (int t = 0; t < af[i].num_elements; t++)
                    af[i].x[t] = wmma::__float_to_tf32(af[i].x[t]);
            }
#pragma unroll
            for (int j = 0; j < 2; j++) {
                wmma::load_matrix_sync(bf[j], &Bs[ks * LDB + wn * 32 + j * 16], LDB);
#pragma unroll
                for (int t = 0; t < bf[j].num_elements; t++)
                    bf[j].x[t] = wmma::__float_to_tf32(bf[j].x[t]);
            }
#pragma unroll
            for (int i = 0; i < 2; i++)
#pragma unroll
                for (int j = 0; j < 2; j++)
                    wmma::mma_sync(acc[i][j], af[i], bf[j], acc[i][j]);
        }
        __syncthreads();
    }

#pragma unroll
    for (int i = 0; i < 2; i++)
#pragma unroll
        for (int j = 0; j < 2; j++)
            wmma::store_matrix_sync(&Cs[(wm * 32 + i * 16) * BN + wn * 32 + j * 16],
                                    acc[i][j], BN, wmma::mem_row_major);
    __syncthreads();
    __half2* C2 = (__half2*)C;
    int ldc2 = N >> 1;
#pragma unroll
    for (int i = 0; i < 16; i++) {
        int lin = tid + i * 128;
        int r = lin >> 5;
        int c2 = lin & 31;
        float lo = Cs[r * BN + 2 * c2];
        float hi = Cs[r * BN + 2 * c2 + 1];
        C2[(long long)(row0 + r) * ldc2 + (col0 >> 1) + c2] = __floats2half2_rn(lo, hi);
    }
}

// ---------------------------------------------------------------------------
// GEMM2: fp16 wmma m16n16k16, A=g_agg1, B=g_W2h, C=g_h2. 64x64 tile.
// ---------------------------------------------------------------------------
__global__ void h16_gemm_kernel(int M) {
    constexpr int K = HID, N = OUTD;
    constexpr int BM = 64, BN = 64, BK = 32;
    constexpr int LDA = BK + 8, LDB = BN + 8;
    __shared__ __half Ah[BM * LDA];
    __shared__ __half Bh[BK * LDB];
    __shared__ float Cs[BM * BN];

    const int tid = threadIdx.x;
    const int wid = tid >> 5;
    const int wm = wid >> 1, wn = wid & 1;
    const int row0 = blockIdx.x * BM;

    wmma::fragment<wmma::accumulator, 16, 16, 16, float> acc[2][2];
#pragma unroll
    for (int i = 0; i < 2; i++)
#pragma unroll
        for (int j = 0; j < 2; j++) wmma::fill_fragment(acc[i][j], 0.0f);

    const __half* A = g_agg1;
    for (int k0 = 0; k0 < K; k0 += BK) {
#pragma unroll
        for (int i = 0; i < 2; i++) {
            int lin = tid + i * 128;
            int r = lin >> 2;
            int c8 = (lin & 3) << 3;
            uint4 v = *reinterpret_cast<const uint4*>(&A[(long long)(row0 + r) * K + k0 + c8]);
            *reinterpret_cast<uint4*>(&Ah[r * LDA + c8]) = v;
        }
#pragma unroll
        for (int i = 0; i < 2; i++) {
            int lin = tid + i * 128;
            int kk = lin >> 3;
            int c8 = (lin & 7) << 3;
            uint4 v = *reinterpret_cast<const uint4*>(&g_W2h[(k0 + kk) * N + c8]);
            *reinterpret_cast<uint4*>(&Bh[kk * LDB + c8]) = v;
        }
        __syncthreads();

#pragma unroll
        for (int ks = 0; ks < BK; ks += 16) {
            wmma::fragment<wmma::matrix_a, 16, 16, 16, __half, wmma::row_major> af[2];
            wmma::fragment<wmma::matrix_b, 16, 16, 16, __half, wmma::row_major> bf[2];
#pragma unroll
            for (int i = 0; i < 2; i++)
                wmma::load_matrix_sync(af[i], &Ah[(wm * 32 + i * 16) * LDA + ks], LDA);
#pragma unroll
            for (int j = 0; j < 2; j++)
                wmma::load_matrix_sync(bf[j], &Bh[ks * LDB + wn * 32 + j * 16], LDB);
#pragma unroll
            for (int i = 0; i < 2; i++)
#pragma unroll
                for (int j = 0; j < 2; j++)
                    wmma::mma_sync(acc[i][j], af[i], bf[j], acc[i][j]);
        }
        __syncthreads();
    }

#pragma unroll
    for (int i = 0; i < 2; i++)
#pragma unroll
        for (int j = 0; j < 2; j++)
            wmma::store_matrix_sync(&Cs[(wm * 32 + i * 16) * BN + wn * 32 + j * 16],
                                    acc[i][j], BN, wmma::mem_row_major);
    __syncthreads();
    __half2* C2 = (__half2*)g_h2;
#pragma unroll
    for (int i = 0; i < 16; i++) {
        int lin = tid + i * 128;
        int r = lin >> 5;
        int c2 = lin & 31;
        float lo = Cs[r * BN + 2 * c2];
        float hi = Cs[r * BN + 2 * c2 + 1];
        C2[(long long)(row0 + r) * (N >> 1) + c2] = __floats2half2_rn(lo, hi);
    }
}

// ---------------------------------------------------------------------------
// Launch: GEMM1 forked onto a non-blocking side stream, overlapping the CSR
// build on the main stream. Fork/join via events (canonical capture pattern).
// ---------------------------------------------------------------------------
extern "C" void kernel_launch(void* const* d_in, const int* in_sizes, int n_in,
                              void* d_out, int out_size) {
    const float* x = (const float*)d_in[0];
    const void* ei = d_in[1];
    const float* W1 = (const float*)d_in[2];
    const float* b1 = (const float*)d_in[3];
    const float* W2 = (const float*)d_in[4];
    const float* b2 = (const float*)d_in[5];
    float* out = (float*)d_out;

    const int Nn = in_sizes[0] / IN_DIM;   // 100000
    const int E = in_sizes[1] / 2;         // 1600000
    const int TB = 256;

    __half* h1_p;
    cudaGetSymbolAddress((void**)&h1_p, g_h1);

    // Side stream + fork/join events. Created fresh per call (host-side only;
    // not device memory). Not destroyed: the capture still references them
    // when kernel_launch returns, and replay never re-runs host code.
    cudaStream_t s2;
    cudaStreamCreateWithFlags(&s2, cudaStreamNonBlocking);
    cudaEvent_t eFork, eJoin;
    cudaEventCreateWithFlags(&eFork, cudaEventDisableTiming);
    cudaEventCreateWithFlags(&eJoin, cudaEventDisableTiming);

    // Fork: s2 branches off the main (capture-origin) stream.
    cudaEventRecord(eFork, 0);
    cudaStreamWaitEvent(s2, eFork, 0);

    // Side stream: GEMM1 (touches only x, W1, g_h1 — disjoint from CSR build)
    {
        dim3 grid(HID / 64, (Nn + 63) / 64);
        tf32_gemm_h_kernel<<<grid, 128, 0, s2>>>(Nn, HID, IN_DIM, x, W1, h1_p);
    }
    cudaEventRecord(eJoin, s2);

    // Main stream: CSR build chain (touches deg/dinv/rowstart/cursor/csr/W2h)
    init_kernel<<<(Nn + TB - 1) / TB, TB>>>(ei, W2, E, Nn);
    count_kernel<<<(E + TB - 1) / TB, TB>>>(ei, E, Nn);
    node_setup_kernel<<<(Nn + TB - 1) / TB, TB>>>(Nn);
    fill_kernel<<<(E + TB - 1) / TB, TB>>>(ei, E, Nn);

    // Join: gather1 needs both g_h1 (s2) and the CSR (main).
    cudaStreamWaitEvent(0, eJoin, 0);

    {
        int blocks = (Nn + (TB / 32) - 1) / (TB / 32);
        gather1_kernel<<<blocks, TB>>>(b1, Nn);
    }
    h16_gemm_kernel<<<(Nn + 63) / 64, 128>>>(Nn);
    {
        int blocks = (Nn + (TB / 32) - 1) / (TB / 32);
        gather2_kernel<<<blocks, TB>>>(b2, out, Nn);
    }
}